// round 16
// baseline (speedup 1.0000x reference)
#include <cuda_runtime.h>
#include <cuda_fp16.h>
#include <cstdint>
#include <math.h>

// ---------------- problem constants ----------------
#define BB 8
#define TT 4096
#define DD 256
#define MM (BB*TT)      // 32768
#define KK 512          // 2*D
#define NCH 2048        // B*D

// scan chunking
#define CHUNK 128
#define NCHUNK (TT/CHUNK)   // 32

// GEMM tiling (both paths: 128x128 tiles, 256 threads)
#define BM 128
#define BN 128
#define TPB 256

// tensor path: BK=32 (2 ktiles of k16), 3-stage smem pipeline
#define BKT 32
#define NCKT (KK/BKT)       // 16 chunks
#define FBUF 8192
#define NSTAGE 3
#define SM_BYTES (NSTAGE * FBUF * 4)    // 96 KB (ffma path uses a 34 KB slice)

// ffma path: BK=16 double-buffered
#define BKF 16
#define NCKF (KK/BKF)       // 32

// M-split: first MSPLIT m-tiles -> tensor path, rest -> ffma path
#define MSPLIT 168

typedef unsigned long long ull;

// ---------------- scratch (allocation-free) ----------------
__device__ float  g_U[(size_t)MM * KK];    // fp32 u
__device__ float  g_S[(size_t)MM * KK];    // fp32 scanned state (ffma path A)
__device__ __half g_Xh[(size_t)MM * KK];   // hi limb of concat(x_re,x_im)
__device__ __half g_Xl[(size_t)MM * KK];
__device__ __half g_Sh[(size_t)MM * KK];   // hi limb of scanned state
__device__ __half g_Sl[(size_t)MM * KK];
__device__ __half g_W0h[512 * 512], g_W0l[512 * 512];   // Wm limbs
__device__ __half g_W1h[768 * 512], g_W1l[768 * 512];   // [Wo;Wg] limbs
__device__ float g_E[2 * NCHUNK * NCH];
__device__ float g_C[2 * NCHUNK * NCH];

// ---------------- helpers ----------------
__device__ __forceinline__ void split_store4(const float4 v, __half* ph, __half* pl, size_t e) {
    __half2 h0 = __floats2half2_rn(v.x, v.y);
    __half2 h1 = __floats2half2_rn(v.z, v.w);
    float2 f0 = __half22float2(h0), f1 = __half22float2(h1);
    __half2 l0 = __floats2half2_rn(v.x - f0.x, v.y - f0.y);
    __half2 l1 = __floats2half2_rn(v.z - f1.x, v.w - f1.y);
    *(uint2*)(ph + e) = make_uint2(*(uint32_t*)&h0, *(uint32_t*)&h1);
    *(uint2*)(pl + e) = make_uint2(*(uint32_t*)&l0, *(uint32_t*)&l1);
}

__device__ __forceinline__ int swzA(int idx) { return idx ^ (((idx >> 5) & 3) << 2); }
__device__ __forceinline__ int swzL(int l) { return l ^ (l >> 3); }

#define MMA_F16(acc, a, bx, by)                                                 \
    asm volatile("mma.sync.aligned.m16n8k16.row.col.f32.f16.f16.f32 "           \
        "{%0,%1,%2,%3}, {%4,%5,%6,%7}, {%8,%9}, {%0,%1,%2,%3};"                 \
        : "+f"((acc)[0]), "+f"((acc)[1]), "+f"((acc)[2]), "+f"((acc)[3])        \
        : "r"((a).x), "r"((a).z), "r"((a).y), "r"((a).w), "r"(bx), "r"(by))

__device__ __forceinline__ ull pack_dup(float x) {
    unsigned u = __float_as_uint(x);
    ull r;
    asm("mov.b64 %0, {%1, %1};" : "=l"(r) : "r"(u));
    return r;
}
__device__ __forceinline__ void fma2(ull& acc, ull a, ull b) {
    asm("fma.rn.f32x2 %0, %1, %2, %0;" : "+l"(acc) : "l"(a), "l"(b));
}
__device__ __forceinline__ float2 unpack2(ull v) {
    unsigned lo, hi;
    asm("mov.b64 {%0, %1}, %2;" : "=r"(lo), "=r"(hi) : "l"(v));
    return make_float2(__uint_as_float(lo), __uint_as_float(hi));
}

// ---------------- pre-split kernels ----------------
__global__ void __launch_bounds__(256)
split_x(const float* __restrict__ xre, const float* __restrict__ xim)
{
    const size_t i = (size_t)blockIdx.x * blockDim.x + threadIdx.x;
    const size_t e = i * 4;
    const int m = (int)(e >> 9);
    const int k = (int)(e & 511);
    const float4 v = (k < 256)
        ? *(const float4*)(xre + (size_t)m * 256 + k)
        : *(const float4*)(xim + (size_t)m * 256 + (k - 256));
    split_store4(v, g_Xh, g_Xl, e);
}

__global__ void __launch_bounds__(256)
split_w(const float* __restrict__ Wm, const float* __restrict__ Wo,
        const float* __restrict__ Wg)
{
    const size_t i = (size_t)blockIdx.x * blockDim.x + threadIdx.x;
    const size_t e = i * 4;
    if (e < (size_t)512 * 512) {
        split_store4(*(const float4*)(Wm + e), g_W0h, g_W0l, e);
    } else {
        const size_t e1 = e - (size_t)512 * 512;
        const int n = (int)(e1 >> 9), k = (int)(e1 & 511);
        const float* src = (n < 512) ? (Wo + (size_t)n * 512 + k)
                                     : (Wg + (size_t)(n - 512) * 512 + k);
        split_store4(*(const float4*)src, g_W1h, g_W1l, e1);
    }
}

// ---------------- hybrid GEMM: tensor path + ffma path ----------------
// C[m,n] = sum_k A[m,k] * W[n,k] + bias[n]
// MODE 0: A = x_cat; W = Wm; C = g_U (ldc=512)
// MODE 1: A = S;     W = Wo (n<512) else Wg (gate: clip(sigmoid)); C = out (ldc=768)
// blockIdx.y < MSPLIT -> 3xFP16 tensor path (pre-split limbs)
// blockIdx.y >= MSPLIT -> packed-FFMA2 fp32 path (original operands)
template <int MODE>
__global__ void __launch_bounds__(TPB)
hy_gemm(const float* __restrict__ Are, const float* __restrict__ Aim,
        const float* __restrict__ W0f, const float* __restrict__ W1f,
        const float* __restrict__ bias0, const float* __restrict__ bias1,
        float* __restrict__ Cout, int ldc)
{
    extern __shared__ uint32_t sm[];

    const int tid = threadIdx.x;
    const int m0 = blockIdx.y * BM;
    const int n0 = blockIdx.x * BN;
    const bool gate = (MODE == 1) && (n0 >= 512);

    if (blockIdx.y < MSPLIT) {
        // ================= tensor path (3xFP16 limbs) =================
        const int wid = tid >> 5;
        const int lane = tid & 31;
        const int warp_m = wid & 3;
        const int warp_n = wid >> 2;

        const __half* __restrict__ Aph = (MODE == 0) ? g_Xh : g_Sh;
        const __half* __restrict__ Apl = (MODE == 0) ? g_Xl : g_Sl;
        const __half* __restrict__ Bph = (MODE == 0) ? g_W0h : g_W1h;
        const __half* __restrict__ Bpl = (MODE == 0) ? g_W0l : g_W1l;

        const int lr = (tid & 15) + ((tid >> 5) << 4);
        const int lh = (tid >> 4) & 1;
        const int lmt = lr >> 4;
        const int lrh = (lr >> 3) & 1;
        const int lnt = lr >> 3;
        const int lg  = lr & 7;

        uint4 sa0, sa1, sl0, sl1, sb0, sb1, sv0, sv1;

        auto fetch = [&](int c) {
            const size_t arow = (size_t)(m0 + lr) * KK + c * BKT + lh * 16;
            sa0 = *(const uint4*)(Aph + arow);
            sa1 = *(const uint4*)(Aph + arow + 8);
            sl0 = *(const uint4*)(Apl + arow);
            sl1 = *(const uint4*)(Apl + arow + 8);
            const size_t brow = (size_t)(n0 + lr) * KK + c * BKT + lh * 16;
            sb0 = *(const uint4*)(Bph + brow);
            sb1 = *(const uint4*)(Bph + brow + 8);
            sv0 = *(const uint4*)(Bpl + brow);
            sv1 = *(const uint4*)(Bpl + brow + 8);
        };

        auto store_smem = [&](int buf) {
            uint32_t* base = sm + buf * FBUF;
            const uint32_t a0[4] = {sa0.x, sa0.y, sa0.z, sa0.w};
            const uint32_t a1[4] = {sa1.x, sa1.y, sa1.z, sa1.w};
            const uint32_t l0[4] = {sl0.x, sl0.y, sl0.z, sl0.w};
            const uint32_t l1[4] = {sl1.x, sl1.y, sl1.z, sl1.w};
            const uint32_t b0[4] = {sb0.x, sb0.y, sb0.z, sb0.w};
            const uint32_t b1[4] = {sb1.x, sb1.y, sb1.z, sb1.w};
            const uint32_t v0[4] = {sv0.x, sv0.y, sv0.z, sv0.w};
            const uint32_t v1[4] = {sv1.x, sv1.y, sv1.z, sv1.w};
#pragma unroll
            for (int t = 0; t < 4; t++) {
                const int lw = lg * 4 + t;
                const int pa = swzA(lh * 1024 + lmt * 128 + lw * 4 + lrh * 2);
                *(uint2*)(base + pa)        = make_uint2(a0[t], a1[t]);
                *(uint2*)(base + 2048 + pa) = make_uint2(l0[t], l1[t]);
                const int pb = 4096 + lh * 2048 + lnt * 128 + swzL(lw) * 4;
                *(uint4*)(base + pb) = make_uint4(b0[t], b1[t], v0[t], v1[t]);
            }
        };

        float acc[2][8][4];
#pragma unroll
        for (int mi = 0; mi < 2; mi++)
#pragma unroll
            for (int ni = 0; ni < 8; ni++)
#pragma unroll
                for (int q = 0; q < 4; q++) acc[mi][ni][q] = 0.0f;

        fetch(0);
        store_smem(0);
        fetch(1);
        __syncthreads();

        const int lsw = swzL(lane) * 4;

#pragma unroll 1
        for (int c = 0; c < NCKT; c++) {
            if (c + 1 < NCKT) store_smem((c + 1) % NSTAGE);
            if (c + 2 < NCKT) fetch(c + 2);
            __syncthreads();

            const uint32_t* base = sm + (c % NSTAGE) * FBUF;

#pragma unroll
            for (int kt = 0; kt < 2; kt++) {
                uint4 ah[2], al[2], bq[8];
#pragma unroll
                for (int mi = 0; mi < 2; mi++) {
                    const int p = swzA(kt * 1024 + (warp_m * 2 + mi) * 128 + lane * 4);
                    ah[mi] = *(const uint4*)(base + p);
                    al[mi] = *(const uint4*)(base + 2048 + p);
                }
#pragma unroll
                for (int ni = 0; ni < 8; ni++) {
                    const int p = 4096 + kt * 2048 + (warp_n * 8 + ni) * 128 + lsw;
                    bq[ni] = *(const uint4*)(base + p);
                }
#pragma unroll
                for (int ni = 0; ni < 8; ni++)
#pragma unroll
                    for (int mi = 0; mi < 2; mi++)
                        MMA_F16(acc[mi][ni], ah[mi], bq[ni].x, bq[ni].y);
#pragma unroll
                for (int ni = 0; ni < 8; ni++)
#pragma unroll
                    for (int mi = 0; mi < 2; mi++)
                        MMA_F16(acc[mi][ni], ah[mi], bq[ni].z, bq[ni].w);
#pragma unroll
                for (int ni = 0; ni < 8; ni++)
#pragma unroll
                    for (int mi = 0; mi < 2; mi++)
                        MMA_F16(acc[mi][ni], al[mi], bq[ni].x, bq[ni].y);
            }
        }

        const int g = lane >> 2, t = lane & 3;
        float* __restrict__ C = (MODE == 0) ? g_U : Cout;
        const float* bptr = (MODE == 0) ? (bias0 + n0)
                          : (gate ? (bias1 + n0 - 512) : (bias0 + n0));

#pragma unroll
        for (int mi = 0; mi < 2; mi++) {
            const int R0 = m0 + warp_m * 32 + mi * 16 + g;
#pragma unroll
            for (int ni = 0; ni < 8; ni++) {
                const int coff = warp_n * 64 + ni * 8 + 2 * t;
                const float2 bb = *(const float2*)(bptr + coff);
                float v0 = acc[mi][ni][0] + bb.x;
                float v1 = acc[mi][ni][1] + bb.y;
                float v2 = acc[mi][ni][2] + bb.x;
                float v3 = acc[mi][ni][3] + bb.y;
                if (gate) {
                    v0 = fminf(fmaxf(1.0f / (1.0f + __expf(-v0)), 0.01f), 0.99f);
                    v1 = fminf(fmaxf(1.0f / (1.0f + __expf(-v1)), 0.01f), 0.99f);
                    v2 = fminf(fmaxf(1.0f / (1.0f + __expf(-v2)), 0.01f), 0.99f);
                    v3 = fminf(fmaxf(1.0f / (1.0f + __expf(-v3)), 0.01f), 0.99f);
                }
                const int col = n0 + coff;
                *(float2*)(C + (size_t)R0 * ldc + col)       = make_float2(v0, v1);
                *(float2*)(C + (size_t)(R0 + 8) * ldc + col) = make_float2(v2, v3);
            }
        }
    } else {
        // ================= ffma path (fp32, packed f32x2) =================
        float* As = (float*)sm;                    // [2][BKF][BM+4]
        float* Bs = As + 2 * BKF * (BM + 4);       // [2][BKF][BN+4]

        const int tm = tid >> 4;
        const int tn = tid & 15;
        const int lr = tid >> 2;
        const int lc = tid & 3;

        const float* __restrict__ Wsel = gate ? W1f : W0f;
        const int nW = gate ? (n0 - 512) : n0;

        float4 a0, a1, b0, b1;

        auto fetchA = [&](int k0) {
            const float* base;
            if (MODE == 0) {
                base = (k0 < 256) ? (Are + (size_t)m0 * DD + k0)
                                  : (Aim + (size_t)m0 * DD + (k0 - 256));
                a0 = *(const float4*)(base + (size_t)lr * DD + lc * 4);
                a1 = *(const float4*)(base + (size_t)(lr + 64) * DD + lc * 4);
            } else {
                base = g_S + (size_t)m0 * KK + k0;
                a0 = *(const float4*)(base + (size_t)lr * KK + lc * 4);
                a1 = *(const float4*)(base + (size_t)(lr + 64) * KK + lc * 4);
            }
        };
        auto fetchB = [&](int k0) {
            const float* base = Wsel + (size_t)nW * KK + k0;
            b0 = *(const float4*)(base + (size_t)lr * KK + lc * 4);
            b1 = *(const float4*)(base + (size_t)(lr + 64) * KK + lc * 4);
        };
        auto store_f = [&](int buf) {
            float* A = As + buf * BKF * (BM + 4);
            float* B = Bs + buf * BKF * (BN + 4);
            const float av0[4] = {a0.x, a0.y, a0.z, a0.w};
            const float av1[4] = {a1.x, a1.y, a1.z, a1.w};
            const float bv0[4] = {b0.x, b0.y, b0.z, b0.w};
            const float bv1[4] = {b1.x, b1.y, b1.z, b1.w};
#pragma unroll
            for (int j = 0; j < 4; j++) {
                A[(lc * 4 + j) * (BM + 4) + lr]      = av0[j];
                A[(lc * 4 + j) * (BM + 4) + lr + 64] = av1[j];
                B[(lc * 4 + j) * (BN + 4) + lr]      = bv0[j];
                B[(lc * 4 + j) * (BN + 4) + lr + 64] = bv1[j];
            }
        };

        fetchA(0); fetchB(0);
        store_f(0);
        __syncthreads();

        ull acc[8][4];
#pragma unroll
        for (int i = 0; i < 8; i++)
#pragma unroll
            for (int p = 0; p < 4; p++) acc[i][p] = 0ull;

#pragma unroll 1
        for (int kt = 0; kt < NCKF; kt++) {
            const int buf = kt & 1;
            const bool has_next = (kt + 1 < NCKF);
            if (has_next) { fetchA((kt + 1) * BKF); fetchB((kt + 1) * BKF); }

            const float* A = As + buf * BKF * (BM + 4);
            const float* B = Bs + buf * BKF * (BN + 4);
#pragma unroll
            for (int k = 0; k < BKF; k++) {
                const float4 av0 = *(const float4*)&A[k * (BM + 4) + tm * 8];
                const float4 av1 = *(const float4*)&A[k * (BM + 4) + tm * 8 + 4];
                const ulonglong2 bv0 = *(const ulonglong2*)&B[k * (BN + 4) + tn * 8];
                const ulonglong2 bv1 = *(const ulonglong2*)&B[k * (BN + 4) + tn * 8 + 4];
                ull ap[8] = {pack_dup(av0.x), pack_dup(av0.y), pack_dup(av0.z), pack_dup(av0.w),
                             pack_dup(av1.x), pack_dup(av1.y), pack_dup(av1.z), pack_dup(av1.w)};
                ull bp[4] = {bv0.x, bv0.y, bv1.x, bv1.y};
#pragma unroll
                for (int i = 0; i < 8; i++)
#pragma unroll
                    for (int p = 0; p < 4; p++)
                        fma2(acc[i][p], ap[i], bp[p]);
            }

            if (has_next) {
                store_f(buf ^ 1);
                __syncthreads();
            }
        }

        const int ncol = n0 + tn * 8;
        float bias[8];
#pragma unroll
        for (int j = 0; j < 8; j++) {
            if (MODE == 0)     bias[j] = bias0[ncol + j];
            else if (gate)     bias[j] = bias1[ncol - 512 + j];
            else               bias[j] = bias0[ncol + j];
        }

        float* __restrict__ C = (MODE == 0) ? g_U : Cout;

#pragma unroll
        for (int i = 0; i < 8; i++) {
            const int m = m0 + tm * 8 + i;
            float v[8];
#pragma unroll
            for (int p = 0; p < 4; p++) {
                float2 f = unpack2(acc[i][p]);
                v[2 * p]     = f.x + bias[2 * p];
                v[2 * p + 1] = f.y + bias[2 * p + 1];
            }
            if (gate) {
#pragma unroll
                for (int j = 0; j < 8; j++) {
                    const float s = 1.0f / (1.0f + __expf(-v[j]));
                    v[j] = fminf(fmaxf(s, 0.01f), 0.99f);
                }
            }
            float* c = C + (size_t)m * ldc + ncol;
            *(float4*)c       = make_float4(v[0], v[1], v[2], v[3]);
            *(float4*)(c + 4) = make_float4(v[4], v[5], v[6], v[7]);
        }
    }
}

// ---------------- chunk-parallel diagonal complex scan ----------------
__global__ void __launch_bounds__(256)
scan_passA(const float* __restrict__ decay_re, const float* __restrict__ decay_im)
{
    const int id = blockIdx.x * blockDim.x + threadIdx.x;
    const int ch = id & (NCH - 1);
    const int c  = id >> 11;
    const int b = ch >> 8;
    const int d = ch & 255;

    const float dr = 1.0f / (1.0f + expf(-decay_re[d]));
    const float di = decay_im[d];

    const float* __restrict__ U = g_U + ((size_t)b * TT + (size_t)c * CHUNK) * KK + d;

    float sr = 0.0f, si = 0.0f;
#pragma unroll 4
    for (int j = 0; j < CHUNK; j++) {
        const float ur = __ldg(U + (size_t)j * KK);
        const float ui = __ldg(U + (size_t)j * KK + 256);
        const float nr = fmaf(sr, dr, fmaf(-si, di, ur));
        const float ni = fmaf(sr, di, fmaf(si, dr, ui));
        sr = nr; si = ni;
    }
    g_E[c * NCH + ch]                = sr;
    g_E[NCHUNK * NCH + c * NCH + ch] = si;
}

__global__ void __launch_bounds__(256)
scan_passB(const float* __restrict__ s0_re, const float* __restrict__ s0_im,
           const float* __restrict__ decay_re, const float* __restrict__ decay_im)
{
    const int id = blockIdx.x * blockDim.x + threadIdx.x;
    const int d = id & 255;

    const float dr = 1.0f / (1.0f + expf(-decay_re[d]));
    const float di = decay_im[d];

    float pr = dr, pi = di;
#pragma unroll
    for (int s = 0; s < 7; s++) {     // d^128
        const float nr = pr * pr - pi * pi;
        const float ni = 2.0f * pr * pi;
        pr = nr; pi = ni;
    }

    float cr = s0_re[id];
    float ci = s0_im[id];
#pragma unroll
    for (int c = 0; c < NCHUNK; c++) {
        g_C[c * NCH + id]                = cr;
        g_C[NCHUNK * NCH + c * NCH + id] = ci;
        const float er = g_E[c * NCH + id];
        const float ei = g_E[NCHUNK * NCH + c * NCH + id];
        const float nr = fmaf(cr, pr, fmaf(-ci, pi, er));
        const float ni = fmaf(cr, pi, fmaf(ci, pr, ei));
        cr = nr; ci = ni;
    }
}

// Pass C: re-scan seeded with carry; write fp32 S + fp16 hi/lo limbs.
__global__ void __launch_bounds__(256)
scan_passC(const float* __restrict__ decay_re, const float* __restrict__ decay_im)
{
    const int id = blockIdx.x * blockDim.x + threadIdx.x;
    const int ch = id & (NCH - 1);
    const int c  = id >> 11;
    const int b = ch >> 8;
    const int d = ch & 255;

    const float dr = 1.0f / (1.0f + expf(-decay_re[d]));
    const float di = decay_im[d];

    const size_t off = ((size_t)b * TT + (size_t)c * CHUNK) * KK + d;
    const float* __restrict__ U = g_U + off;

    float sr = g_C[c * NCH + ch];
    float si = g_C[NCHUNK * NCH + c * NCH + ch];

#pragma unroll 4
    for (int j = 0; j < CHUNK; j++) {
        const float ur = __ldg(U + (size_t)j * KK);
        const float ui = __ldg(U + (size_t)j * KK + 256);
        const float nr = fmaf(sr, dr, fmaf(-si, di, ur));
        const float ni = fmaf(sr, di, fmaf(si, dr, ui));
        sr = nr; si = ni;
        const size_t a = off + (size_t)j * KK;
        g_S[a]       = nr;
        g_S[a + 256] = ni;
        const __half hr = __float2half_rn(nr);
        const __half hi = __float2half_rn(ni);
        g_Sh[a]       = hr;
        g_Sh[a + 256] = hi;
        g_Sl[a]       = __float2half_rn(nr - __half2float(hr));
        g_Sl[a + 256] = __float2half_rn(ni - __half2float(hi));
    }
}

// ---------------- launch ----------------
extern "C" void kernel_launch(void* const* d_in, const int* in_sizes, int n_in,
                              void* d_out, int out_size)
{
    (void)in_sizes; (void)n_in; (void)out_size;
    const float* x_re     = (const float*)d_in[0];
    const float* x_im     = (const float*)d_in[1];
    const float* s0_re    = (const float*)d_in[2];
    const float* s0_im    = (const float*)d_in[3];
    const float* decay_re = (const float*)d_in[4];
    const float* decay_im = (const float*)d_in[5];
    const float* Wm       = (const float*)d_in[6];
    const float* bm       = (const float*)d_in[7];
    const float* Wo       = (const float*)d_in[8];
    const float* bo       = (const float*)d_in[9];
    const float* Wg       = (const float*)d_in[10];
    const float* bg       = (const float*)d_in[11];
    float* out = (float*)d_out;

    static bool configured = false;
    if (!configured) {
        cudaFuncSetAttribute(hy_gemm<0>, cudaFuncAttributeMaxDynamicSharedMemorySize, SM_BYTES);
        cudaFuncSetAttribute(hy_gemm<1>, cudaFuncAttributeMaxDynamicSharedMemorySize, SM_BYTES);
        configured = true;
    }

    // 0) pre-split inputs and weights into fp16 limb planes
    split_x<<<(MM * KK / 4) / 256, 256>>>(x_re, x_im);
    split_w<<<((512 * 512 + 768 * 512) / 4) / 256, 256>>>(Wm, Wo, Wg);

    // 1) u = x_cat @ Wm^T + bm  -> g_U (fp32)
    hy_gemm<0><<<dim3(KK / BN, MM / BM), TPB, SM_BYTES>>>(
        x_re, x_im, Wm, nullptr, bm, nullptr, nullptr, KK);

    // 2) chunk-parallel diagonal complex scan g_U -> g_S (+ fp16 limbs)
    scan_passA<<<(NCH * NCHUNK) / 256, 256>>>(decay_re, decay_im);
    scan_passB<<<NCH / 256, 256>>>(s0_re, s0_im, decay_re, decay_im);
    scan_passC<<<(NCH * NCHUNK) / 256, 256>>>(decay_re, decay_im);

    // 3) [source | gate] = s_cat @ [Wo;Wg]^T + [bo;bg]
    hy_gemm<1><<<dim3(768 / BN, MM / BM), TPB, SM_BYTES>>>(
        nullptr, nullptr, Wo, Wg, bo, bg, out, 768);
}

// round 17
// speedup vs baseline: 1.1082x; 1.1082x over previous
#include <cuda_runtime.h>
#include <cuda_fp16.h>
#include <cstdint>
#include <math.h>

// ---------------- problem constants ----------------
#define BB 8
#define TT 4096
#define DD 256
#define MM (BB*TT)      // 32768
#define KK 512          // 2*D
#define NCH 2048        // B*D

// scan chunking
#define CHUNK 128
#define NCHUNK (TT/CHUNK)   // 32

// mma.sync fp16 GEMM tiling
#define BM 128
#define BN 128
#define BKT 32              // K per chunk (2 ktiles of k16)
#define NCKT (KK/BKT)       // 16 chunks
#define TPB 256

// smem per stage (b32 words): A hi [0,2048) lo [2048,4096); B interleaved [4096,8192)
#define FBUF 8192
#define NSTAGE 2
#define SM_BYTES (NSTAGE * FBUF * 4)    // 64 KB -> 2 CTAs/SM

// ---------------- scratch (allocation-free) ----------------
__device__ float  g_U[(size_t)MM * KK];    // fp32 u (scan input)
__device__ __half g_Xh[(size_t)MM * KK];   // hi limb of concat(x_re,x_im)
__device__ __half g_Xl[(size_t)MM * KK];
__device__ __half g_Sh[(size_t)MM * KK];   // hi limb of scanned state
__device__ __half g_Sl[(size_t)MM * KK];
__device__ __half g_W0h[512 * 512], g_W0l[512 * 512];   // Wm limbs
__device__ __half g_W1h[768 * 512], g_W1l[768 * 512];   // [Wo;Wg] limbs
__device__ float g_E[2 * NCHUNK * NCH];
__device__ float g_C[2 * NCHUNK * NCH];

// ---------------- helpers ----------------
__device__ __forceinline__ void split_store4(const float4 v, __half* ph, __half* pl, size_t e) {
    __half2 h0 = __floats2half2_rn(v.x, v.y);
    __half2 h1 = __floats2half2_rn(v.z, v.w);
    float2 f0 = __half22float2(h0), f1 = __half22float2(h1);
    __half2 l0 = __floats2half2_rn(v.x - f0.x, v.y - f0.y);
    __half2 l1 = __floats2half2_rn(v.z - f1.x, v.w - f1.y);
    *(uint2*)(ph + e) = make_uint2(*(uint32_t*)&h0, *(uint32_t*)&h1);
    *(uint2*)(pl + e) = make_uint2(*(uint32_t*)&l0, *(uint32_t*)&l1);
}

__device__ __forceinline__ int swzA(int idx) { return idx ^ (((idx >> 5) & 3) << 2); }
__device__ __forceinline__ int swzL(int l) { return l ^ (l >> 3); }

#define MMA_F16(acc, a, bx, by)                                                 \
    asm volatile("mma.sync.aligned.m16n8k16.row.col.f32.f16.f16.f32 "           \
        "{%0,%1,%2,%3}, {%4,%5,%6,%7}, {%8,%9}, {%0,%1,%2,%3};"                 \
        : "+f"((acc)[0]), "+f"((acc)[1]), "+f"((acc)[2]), "+f"((acc)[3])        \
        : "r"((a).x), "r"((a).z), "r"((a).y), "r"((a).w), "r"(bx), "r"(by))

// ---------------- pre-split kernels ----------------
__global__ void __launch_bounds__(256)
split_x(const float* __restrict__ xre, const float* __restrict__ xim)
{
    const size_t i = (size_t)blockIdx.x * blockDim.x + threadIdx.x;
    const size_t e = i * 4;
    const int m = (int)(e >> 9);
    const int k = (int)(e & 511);
    const float4 v = (k < 256)
        ? *(const float4*)(xre + (size_t)m * 256 + k)
        : *(const float4*)(xim + (size_t)m * 256 + (k - 256));
    split_store4(v, g_Xh, g_Xl, e);
}

__global__ void __launch_bounds__(256)
split_w(const float* __restrict__ Wm, const float* __restrict__ Wo,
        const float* __restrict__ Wg)
{
    const size_t i = (size_t)blockIdx.x * blockDim.x + threadIdx.x;
    const size_t e = i * 4;
    if (e < (size_t)512 * 512) {
        split_store4(*(const float4*)(Wm + e), g_W0h, g_W0l, e);
    } else {
        const size_t e1 = e - (size_t)512 * 512;
        const int n = (int)(e1 >> 9), k = (int)(e1 & 511);
        const float* src = (n < 512) ? (Wo + (size_t)n * 512 + k)
                                     : (Wg + (size_t)(n - 512) * 512 + k);
        split_store4(*(const float4*)src, g_W1h, g_W1l, e1);
    }
}

// ---------------- 3xFP16 mma.sync GEMM (occupancy 2) ----------------
// C[m,n] = sum_k A[m,k] * W[n,k] + bias[n]
// MODE 0: A = g_X limbs; W = g_W0 limbs; C = g_U fp32 (ldc=512)
// MODE 1: A = g_S limbs; W = g_W1 limbs; gate cols (n>=512): clip(sigmoid); C = out (ldc=768)
template <int MODE>
__global__ void __launch_bounds__(TPB, 2)
tc_gemm(const float* __restrict__ bias0, const float* __restrict__ bias1,
        float* __restrict__ Cout, int ldc)
{
    extern __shared__ uint32_t sm[];

    const int tid = threadIdx.x;
    const int wid = tid >> 5;
    const int lane = tid & 31;
    const int warp_m = wid & 3;      // rows warp_m*32
    const int warp_n = wid >> 2;     // cols warp_n*64
    const int m0 = blockIdx.y * BM;
    const int n0 = blockIdx.x * BN;

    const bool gate = (MODE == 1) && (n0 >= 512);

    const __half* __restrict__ Aph = (MODE == 0) ? g_Xh : g_Sh;
    const __half* __restrict__ Apl = (MODE == 0) ? g_Xl : g_Sl;
    const __half* __restrict__ Bph = (MODE == 0) ? g_W0h : g_W1h;
    const __half* __restrict__ Bpl = (MODE == 0) ? g_W0l : g_W1l;

    // loader mapping: row lr (0..127), ktile lh (0/1)
    const int lr = (tid & 15) + ((tid >> 5) << 4);
    const int lh = (tid >> 4) & 1;
    const int lmt = lr >> 4;
    const int lrh = (lr >> 3) & 1;
    const int lnt = lr >> 3;
    const int lg  = lr & 7;

    uint4 sa0, sa1, sl0, sl1, sb0, sb1, sv0, sv1;

    auto fetch = [&](int c) {
        const size_t arow = (size_t)(m0 + lr) * KK + c * BKT + lh * 16;
        sa0 = *(const uint4*)(Aph + arow);
        sa1 = *(const uint4*)(Aph + arow + 8);
        sl0 = *(const uint4*)(Apl + arow);
        sl1 = *(const uint4*)(Apl + arow + 8);
        const size_t brow = (size_t)(n0 + lr) * KK + c * BKT + lh * 16;
        sb0 = *(const uint4*)(Bph + brow);
        sb1 = *(const uint4*)(Bph + brow + 8);
        sv0 = *(const uint4*)(Bpl + brow);
        sv1 = *(const uint4*)(Bpl + brow + 8);
    };

    auto store_smem = [&](int buf) {
        uint32_t* base = sm + buf * FBUF;
        const uint32_t a0[4] = {sa0.x, sa0.y, sa0.z, sa0.w};
        const uint32_t a1[4] = {sa1.x, sa1.y, sa1.z, sa1.w};
        const uint32_t l0[4] = {sl0.x, sl0.y, sl0.z, sl0.w};
        const uint32_t l1[4] = {sl1.x, sl1.y, sl1.z, sl1.w};
        const uint32_t b0[4] = {sb0.x, sb0.y, sb0.z, sb0.w};
        const uint32_t b1[4] = {sb1.x, sb1.y, sb1.z, sb1.w};
        const uint32_t v0[4] = {sv0.x, sv0.y, sv0.z, sv0.w};
        const uint32_t v1[4] = {sv1.x, sv1.y, sv1.z, sv1.w};
#pragma unroll
        for (int t = 0; t < 4; t++) {
            const int lw = lg * 4 + t;
            const int pa = swzA(lh * 1024 + lmt * 128 + lw * 4 + lrh * 2);
            *(uint2*)(base + pa)        = make_uint2(a0[t], a1[t]);
            *(uint2*)(base + 2048 + pa) = make_uint2(l0[t], l1[t]);
            const int pb = 4096 + lh * 2048 + lnt * 128 + swzL(lw) * 4;
            *(uint4*)(base + pb) = make_uint4(b0[t], b1[t], v0[t], v1[t]);
        }
    };

    float acc[2][8][4];
#pragma unroll
    for (int mi = 0; mi < 2; mi++)
#pragma unroll
        for (int ni = 0; ni < 8; ni++)
#pragma unroll
            for (int q = 0; q < 4; q++) acc[mi][ni][q] = 0.0f;

    // prologue: stage 0 in smem, chunk 1 staged in regs
    fetch(0);
    store_smem(0);
    fetch(1);
    __syncthreads();

    const int lsw = swzL(lane) * 4;

#pragma unroll 1
    for (int c = 0; c < NCKT; c++) {
        const uint32_t* base = sm + (c & 1) * FBUF;

#pragma unroll
        for (int kt = 0; kt < 2; kt++) {
            uint4 ah[2], al[2], bq[8];
#pragma unroll
            for (int mi = 0; mi < 2; mi++) {
                const int p = swzA(kt * 1024 + (warp_m * 2 + mi) * 128 + lane * 4);
                ah[mi] = *(const uint4*)(base + p);
                al[mi] = *(const uint4*)(base + 2048 + p);
            }
#pragma unroll
            for (int ni = 0; ni < 8; ni++) {
                const int p = 4096 + kt * 2048 + (warp_n * 8 + ni) * 128 + lsw;
                bq[ni] = *(const uint4*)(base + p);
            }
            // acc-spaced passes: 16 independent accumulators between same-acc mma
#pragma unroll
            for (int ni = 0; ni < 8; ni++)
#pragma unroll
                for (int mi = 0; mi < 2; mi++)
                    MMA_F16(acc[mi][ni], ah[mi], bq[ni].x, bq[ni].y);
#pragma unroll
            for (int ni = 0; ni < 8; ni++)
#pragma unroll
                for (int mi = 0; mi < 2; mi++)
                    MMA_F16(acc[mi][ni], ah[mi], bq[ni].z, bq[ni].w);
#pragma unroll
            for (int ni = 0; ni < 8; ni++)
#pragma unroll
                for (int mi = 0; mi < 2; mi++)
                    MMA_F16(acc[mi][ni], al[mi], bq[ni].x, bq[ni].y);
        }

        // store staged chunk c+1 into the buffer chunk c-1 used, then prefetch c+2
        if (c + 1 < NCKT) {
            store_smem((c + 1) & 1);
            if (c + 2 < NCKT) fetch(c + 2);
            __syncthreads();
        }
    }

    // ---- epilogue ----
    const int g = lane >> 2, t = lane & 3;
    float* __restrict__ C = (MODE == 0) ? g_U : Cout;
    const float* bptr = (MODE == 0) ? (bias0 + n0)
                      : (gate ? (bias1 + n0 - 512) : (bias0 + n0));

#pragma unroll
    for (int mi = 0; mi < 2; mi++) {
        const int R0 = m0 + warp_m * 32 + mi * 16 + g;
#pragma unroll
        for (int ni = 0; ni < 8; ni++) {
            const int coff = warp_n * 64 + ni * 8 + 2 * t;
            const float2 bb = *(const float2*)(bptr + coff);
            float v0 = acc[mi][ni][0] + bb.x;
            float v1 = acc[mi][ni][1] + bb.y;
            float v2 = acc[mi][ni][2] + bb.x;
            float v3 = acc[mi][ni][3] + bb.y;
            if (gate) {
                v0 = fminf(fmaxf(1.0f / (1.0f + __expf(-v0)), 0.01f), 0.99f);
                v1 = fminf(fmaxf(1.0f / (1.0f + __expf(-v1)), 0.01f), 0.99f);
                v2 = fminf(fmaxf(1.0f / (1.0f + __expf(-v2)), 0.01f), 0.99f);
                v3 = fminf(fmaxf(1.0f / (1.0f + __expf(-v3)), 0.01f), 0.99f);
            }
            const int col = n0 + coff;
            *(float2*)(C + (size_t)R0 * ldc + col)       = make_float2(v0, v1);
            *(float2*)(C + (size_t)(R0 + 8) * ldc + col) = make_float2(v2, v3);
        }
    }
}

// ---------------- chunk-parallel diagonal complex scan ----------------
__global__ void __launch_bounds__(256)
scan_passA(const float* __restrict__ decay_re, const float* __restrict__ decay_im)
{
    const int id = blockIdx.x * blockDim.x + threadIdx.x;
    const int ch = id & (NCH - 1);
    const int c  = id >> 11;
    const int b = ch >> 8;
    const int d = ch & 255;

    const float dr = 1.0f / (1.0f + expf(-decay_re[d]));
    const float di = decay_im[d];

    const float* __restrict__ U = g_U + ((size_t)b * TT + (size_t)c * CHUNK) * KK + d;

    float sr = 0.0f, si = 0.0f;
#pragma unroll 4
    for (int j = 0; j < CHUNK; j++) {
        const float ur = __ldg(U + (size_t)j * KK);
        const float ui = __ldg(U + (size_t)j * KK + 256);
        const float nr = fmaf(sr, dr, fmaf(-si, di, ur));
        const float ni = fmaf(sr, di, fmaf(si, dr, ui));
        sr = nr; si = ni;
    }
    g_E[c * NCH + ch]                = sr;
    g_E[NCHUNK * NCH + c * NCH + ch] = si;
}

__global__ void __launch_bounds__(256)
scan_passB(const float* __restrict__ s0_re, const float* __restrict__ s0_im,
           const float* __restrict__ decay_re, const float* __restrict__ decay_im)
{
    const int id = blockIdx.x * blockDim.x + threadIdx.x;
    const int d = id & 255;

    const float dr = 1.0f / (1.0f + expf(-decay_re[d]));
    const float di = decay_im[d];

    float pr = dr, pi = di;
#pragma unroll
    for (int s = 0; s < 7; s++) {     // d^128
        const float nr = pr * pr - pi * pi;
        const float ni = 2.0f * pr * pi;
        pr = nr; pi = ni;
    }

    float cr = s0_re[id];
    float ci = s0_im[id];
#pragma unroll
    for (int c = 0; c < NCHUNK; c++) {
        g_C[c * NCH + id]                = cr;
        g_C[NCHUNK * NCH + c * NCH + id] = ci;
        const float er = g_E[c * NCH + id];
        const float ei = g_E[NCHUNK * NCH + c * NCH + id];
        const float nr = fmaf(cr, pr, fmaf(-ci, pi, er));
        const float ni = fmaf(cr, pi, fmaf(ci, pr, ei));
        cr = nr; ci = ni;
    }
}

// Pass C: re-scan seeded with carry; write fp16 hi/lo limbs of S directly.
__global__ void __launch_bounds__(256)
scan_passC(const float* __restrict__ decay_re, const float* __restrict__ decay_im)
{
    const int id = blockIdx.x * blockDim.x + threadIdx.x;
    const int ch = id & (NCH - 1);
    const int c  = id >> 11;
    const int b = ch >> 8;
    const int d = ch & 255;

    const float dr = 1.0f / (1.0f + expf(-decay_re[d]));
    const float di = decay_im[d];

    const size_t off = ((size_t)b * TT + (size_t)c * CHUNK) * KK + d;
    const float* __restrict__ U = g_U + off;

    float sr = g_C[c * NCH + ch];
    float si = g_C[NCHUNK * NCH + c * NCH + ch];

#pragma unroll 4
    for (int j = 0; j < CHUNK; j++) {
        const float ur = __ldg(U + (size_t)j * KK);
        const float ui = __ldg(U + (size_t)j * KK + 256);
        const float nr = fmaf(sr, dr, fmaf(-si, di, ur));
        const float ni = fmaf(sr, di, fmaf(si, dr, ui));
        sr = nr; si = ni;
        const size_t a = off + (size_t)j * KK;
        const __half hr = __float2half_rn(nr);
        const __half hi = __float2half_rn(ni);
        g_Sh[a]       = hr;
        g_Sh[a + 256] = hi;
        g_Sl[a]       = __float2half_rn(nr - __half2float(hr));
        g_Sl[a + 256] = __float2half_rn(ni - __half2float(hi));
    }
}

// ---------------- launch ----------------
extern "C" void kernel_launch(void* const* d_in, const int* in_sizes, int n_in,
                              void* d_out, int out_size)
{
    (void)in_sizes; (void)n_in; (void)out_size;
    const float* x_re     = (const float*)d_in[0];
    const float* x_im     = (const float*)d_in[1];
    const float* s0_re    = (const float*)d_in[2];
    const float* s0_im    = (const float*)d_in[3];
    const float* decay_re = (const float*)d_in[4];
    const float* decay_im = (const float*)d_in[5];
    const float* Wm       = (const float*)d_in[6];
    const float* bm       = (const float*)d_in[7];
    const float* Wo       = (const float*)d_in[8];
    const float* bo       = (const float*)d_in[9];
    const float* Wg       = (const float*)d_in[10];
    const float* bg       = (const float*)d_in[11];
    float* out = (float*)d_out;

    static bool configured = false;
    if (!configured) {
        cudaFuncSetAttribute(tc_gemm<0>, cudaFuncAttributeMaxDynamicSharedMemorySize, SM_BYTES);
        cudaFuncSetAttribute(tc_gemm<1>, cudaFuncAttributeMaxDynamicSharedMemorySize, SM_BYTES);
        configured = true;
    }

    // 0) pre-split inputs and weights into fp16 limb planes
    split_x<<<(MM * KK / 4) / 256, 256>>>(x_re, x_im);
    split_w<<<((512 * 512 + 768 * 512) / 4) / 256, 256>>>(Wm, Wo, Wg);

    // 1) u = x_cat @ Wm^T + bm  -> g_U (fp32)
    tc_gemm<0><<<dim3(KK / BN, MM / BM), TPB, SM_BYTES>>>(bm, nullptr, nullptr, KK);

    // 2) chunk-parallel diagonal complex scan g_U -> g_Sh/g_Sl (fp16 limbs)
    scan_passA<<<(NCH * NCHUNK) / 256, 256>>>(decay_re, decay_im);
    scan_passB<<<NCH / 256, 256>>>(s0_re, s0_im, decay_re, decay_im);
    scan_passC<<<(NCH * NCHUNK) / 256, 256>>>(decay_re, decay_im);

    // 3) [source | gate] = s_cat @ [Wo;Wg]^T + [bo;bg]
    tc_gemm<1><<<dim3(768 / BN, MM / BM), TPB, SM_BYTES>>>(bo, bg, out, 768);
}